// round 1
// baseline (speedup 1.0000x reference)
#include <cuda_runtime.h>
#include <math.h>

// Problem dims (fixed by setup_inputs)
#define B_    8
#define NPT   8192          // n (queries per batch)
#define MPT   2048          // m (known per batch)
#define C_    256           // C1 == C2
#define H_    512           // hidden = Cin = H1 = H2
#define NTOT  (B_ * NPT)    // 65536 columns
#define GK    512
#define GM    512

// ---------------- scratch ----------------
__device__ float g_X[(size_t)H_ * NTOT];   // concat(interp, unknow_feats): [512][65536]
__device__ float g_Y[(size_t)H_ * NTOT];   // layer-1 output
__device__ int   g_idx[NTOT * 3];
__device__ float g_w[NTOT * 3];

// ---------------- kernel 1: brute-force 3-NN + weights ----------------
__global__ __launch_bounds__(256)
void knn_kernel(const float* __restrict__ unknown, const float* __restrict__ known)
{
    __shared__ float kx[MPT], ky[MPT], kz[MPT];
    const int b = blockIdx.y;
    const float* kb = known + (size_t)b * MPT * 3;
    for (int i = threadIdx.x; i < MPT; i += 256) {
        kx[i] = kb[i * 3 + 0];
        ky[i] = kb[i * 3 + 1];
        kz[i] = kb[i * 3 + 2];
    }
    __syncthreads();

    const int q = blockIdx.x * 256 + threadIdx.x;      // 0..8191
    const float* up = unknown + ((size_t)b * NPT + q) * 3;
    const float ux = up[0], uy = up[1], uz = up[2];

    float d0 = 1e30f, d1 = 1e30f, d2 = 1e30f;
    int   i0 = 0,     i1 = 0,     i2 = 0;

    #pragma unroll 4
    for (int i = 0; i < MPT; i++) {
        float dx = kx[i] - ux;
        float dy = ky[i] - uy;
        float dz = kz[i] - uz;
        float d  = dx * dx + dy * dy + dz * dz;
        if (d < d2) {
            if (d < d1) {
                if (d < d0) { d2 = d1; i2 = i1; d1 = d0; i1 = i0; d0 = d; i0 = i; }
                else        { d2 = d1; i2 = i1; d1 = d;  i1 = i; }
            } else          { d2 = d;  i2 = i; }
        }
    }

    // weights = recip / sum(recip), on SQUARED distances (matches reference)
    const float r0 = 1.0f / (d0 + 1e-8f);
    const float r1 = 1.0f / (d1 + 1e-8f);
    const float r2 = 1.0f / (d2 + 1e-8f);
    const float s  = 1.0f / (r0 + r1 + r2);

    const int gi = b * NPT + q;
    g_idx[gi * 3 + 0] = i0;
    g_idx[gi * 3 + 1] = i1;
    g_idx[gi * 3 + 2] = i2;
    g_w[gi * 3 + 0] = r0 * s;
    g_w[gi * 3 + 1] = r1 * s;
    g_w[gi * 3 + 2] = r2 * s;
}

// ---------------- kernel 2: three_interpolate + concat into g_X ----------------
// g_X layout: row c (0..511), column p = b*8192 + j.
//   rows [0,256)   = interpolated known_feats
//   rows [256,512) = unknow_feats copy
__global__ __launch_bounds__(256)
void interp_concat_kernel(const float* __restrict__ known_feats,
                          const float* __restrict__ unknow_feats)
{
    const int p = blockIdx.x * 256 + threadIdx.x;      // 0..65535
    const int b = p >> 13;
    const int j = p & (NPT - 1);

    const int   i0 = g_idx[p * 3 + 0];
    const int   i1 = g_idx[p * 3 + 1];
    const int   i2 = g_idx[p * 3 + 2];
    const float w0 = g_w[p * 3 + 0];
    const float w1 = g_w[p * 3 + 1];
    const float w2 = g_w[p * 3 + 2];

    const float* kfb = known_feats  + (size_t)b * C_ * MPT;
    const float* ufb = unknow_feats + (size_t)b * C_ * NPT + j;

    #pragma unroll 4
    for (int c = 0; c < C_; c++) {
        const float* row = kfb + (size_t)c * MPT;
        float v = w0 * __ldg(row + i0) + w1 * __ldg(row + i1) + w2 * __ldg(row + i2);
        g_X[(size_t)c * NTOT + p]        = v;
        g_X[(size_t)(C_ + c) * NTOT + p] = ufb[(size_t)c * NPT];
    }
}

// ---------------- kernel 3: SGEMM (512 x 65536 x 512) + BN + ReLU ----------------
// C[o,p] = relu( (sum_k W[o,k]*X[k,p]) * scale[o] + shift[o] )
// to_out == 0 : write Y[o*65536 + p]
// to_out == 1 : write d_out[(p>>13)*512*8192 + o*8192 + (p&8191)]
__global__ __launch_bounds__(256)
void gemm_bn_relu_kernel(const float* __restrict__ W, const float* __restrict__ X,
                         float* __restrict__ Y,
                         const float* __restrict__ gg, const float* __restrict__ bb,
                         const float* __restrict__ mm, const float* __restrict__ vv,
                         int to_out)
{
    __shared__ float As[16][128];   // [k][m]
    __shared__ float Bs[16][128];   // [k][n]

    const int m0 = blockIdx.y * 128;
    const int n0 = blockIdx.x * 128;
    const int tid = threadIdx.x;           // 0..255
    const int tx = tid & 15;               // n dir
    const int ty = tid >> 4;               // m dir

    float acc[8][8];
    #pragma unroll
    for (int i = 0; i < 8; i++)
        #pragma unroll
        for (int j = 0; j < 8; j++) acc[i][j] = 0.0f;

    for (int k0 = 0; k0 < GK; k0 += 16) {
        // Load W tile 128x16 (transposed into As[k][m]); float4 along k.
        #pragma unroll
        for (int l = 0; l < 2; l++) {
            int idx = tid + l * 256;       // 0..511
            int row = idx >> 2;            // 0..127
            int kq  = (idx & 3) * 4;       // 0,4,8,12
            float4 v = *(const float4*)(&W[(size_t)(m0 + row) * GK + k0 + kq]);
            As[kq + 0][row] = v.x;
            As[kq + 1][row] = v.y;
            As[kq + 2][row] = v.z;
            As[kq + 3][row] = v.w;
        }
        // Load X tile 16x128; float4 along n (coalesced).
        #pragma unroll
        for (int l = 0; l < 2; l++) {
            int idx = tid + l * 256;       // 0..511
            int row = idx >> 5;            // 0..15
            int cq  = (idx & 31) * 4;
            float4 v = *(const float4*)(&X[(size_t)(k0 + row) * NTOT + n0 + cq]);
            *(float4*)(&Bs[row][cq]) = v;
        }
        __syncthreads();

        #pragma unroll
        for (int kk = 0; kk < 16; kk++) {
            float a[8], bvec[8];
            #pragma unroll
            for (int i = 0; i < 2; i++)
                *(float4*)(&a[i * 4]) = *(const float4*)(&As[kk][ty * 8 + i * 4]);
            #pragma unroll
            for (int j = 0; j < 2; j++)
                *(float4*)(&bvec[j * 4]) = *(const float4*)(&Bs[kk][tx * 8 + j * 4]);
            #pragma unroll
            for (int i = 0; i < 8; i++)
                #pragma unroll
                for (int j = 0; j < 8; j++)
                    acc[i][j] = fmaf(a[i], bvec[j], acc[i][j]);
        }
        __syncthreads();
    }

    // Epilogue: inference-BN + ReLU
    #pragma unroll
    for (int i = 0; i < 8; i++) {
        const int o = m0 + ty * 8 + i;
        const float sc = gg[o] * rsqrtf(vv[o] + 1e-5f);
        const float sh = bb[o] - mm[o] * sc;
        #pragma unroll
        for (int j = 0; j < 8; j++) {
            const int p = n0 + tx * 8 + j;
            const float v = fmaxf(fmaf(acc[i][j], sc, sh), 0.0f);
            if (to_out == 0) {
                Y[(size_t)o * NTOT + p] = v;
            } else {
                const int bb_ = p >> 13;
                const int jj  = p & (NPT - 1);
                Y[((size_t)bb_ * H_ + o) * NPT + jj] = v;
            }
        }
    }
}

// ---------------- launch ----------------
extern "C" void kernel_launch(void* const* d_in, const int* in_sizes, int n_in,
                              void* d_out, int out_size)
{
    const float* unknown      = (const float*)d_in[0];   // (8,8192,3)
    const float* known        = (const float*)d_in[1];   // (8,2048,3)
    const float* unknow_feats = (const float*)d_in[2];   // (8,256,8192)
    const float* known_feats  = (const float*)d_in[3];   // (8,256,2048)
    const float* W1 = (const float*)d_in[4];
    const float* g1 = (const float*)d_in[5];
    const float* b1 = (const float*)d_in[6];
    const float* m1 = (const float*)d_in[7];
    const float* v1 = (const float*)d_in[8];
    const float* W2 = (const float*)d_in[9];
    const float* g2 = (const float*)d_in[10];
    const float* b2 = (const float*)d_in[11];
    const float* m2 = (const float*)d_in[12];
    const float* v2 = (const float*)d_in[13];
    float* out = (float*)d_out;

    float* X; cudaGetSymbolAddress((void**)&X, g_X);
    float* Y; cudaGetSymbolAddress((void**)&Y, g_Y);

    // 1) 3-NN + weights
    {
        dim3 grid(NPT / 256, B_);
        knn_kernel<<<grid, 256>>>(unknown, known);
    }
    // 2) interpolate + concat -> g_X (512 x 65536)
    {
        interp_concat_kernel<<<NTOT / 256, 256>>>(known_feats, unknow_feats);
    }
    // 3) layer 1: Y = relu(BN(W1 @ X))
    {
        dim3 grid(NTOT / 128, GM / 128);
        gemm_bn_relu_kernel<<<grid, 256>>>(W1, X, Y, g1, b1, m1, v1, 0);
    }
    // 4) layer 2: out = relu(BN(W2 @ Y)), scattered to (B,512,8192)
    {
        dim3 grid(NTOT / 128, GM / 128);
        gemm_bn_relu_kernel<<<grid, 256>>>(W2, Y, out, g2, b2, m2, v2, 1);
    }
    (void)in_sizes; (void)n_in; (void)out_size;
}

// round 3
// speedup vs baseline: 2.5872x; 2.5872x over previous
#include <cuda_runtime.h>
#include <cstdint>
#include <math.h>

#define B_    8
#define NPT   8192
#define MPT   2048
#define C_    256
#define H_    512
#define NTOT  (B_*NPT)

// ---------------- scratch (device globals; no runtime alloc) ----------------
__device__ float g_X[(size_t)NTOT * H_];          // [p][k] layer-1 input (tf32-rounded)
__device__ float g_Y[(size_t)NTOT * H_];          // [p][o] layer-1 output (tf32-rounded)
__device__ float g_kft[(size_t)B_ * MPT * C_];    // known_feats transposed [b][m][c]
__device__ float g_W1r[H_ * H_];
__device__ float g_W2r[H_ * H_];
__device__ int   g_idx[NTOT * 3];
__device__ float g_w[NTOT * 3];

__device__ __forceinline__ float tf32r(float x) {
    asm("cvt.rna.tf32.f32 %0, %1;" : "=f"(x) : "f"(x));
    return x;
}
__device__ __forceinline__ void cp16(void* s, const void* g) {
    uint32_t a;
    asm("{ .reg .u64 t; cvta.to.shared.u64 t, %1; cvt.u32.u64 %0, t; }" : "=r"(a) : "l"(s));
    asm volatile("cp.async.cg.shared.global [%0], [%1], 16;\n" :: "r"(a), "l"(g));
}

// ---------------- kernel: round weights to tf32 ----------------
__global__ __launch_bounds__(256)
void round_w(const float* __restrict__ W1, const float* __restrict__ W2)
{
    int i = blockIdx.x * 256 + threadIdx.x;
    g_W1r[i] = tf32r(W1[i]);
    g_W2r[i] = tf32r(W2[i]);
}

// ---------------- kernel: 3-NN + weights ----------------
__global__ __launch_bounds__(256)
void knn_kernel(const float* __restrict__ unknown, const float* __restrict__ known)
{
    __shared__ float kx[MPT], ky[MPT], kz[MPT];
    const int b = blockIdx.y;
    const float* kb = known + (size_t)b * MPT * 3;
    for (int i = threadIdx.x; i < MPT; i += 256) {
        kx[i] = kb[i*3+0]; ky[i] = kb[i*3+1]; kz[i] = kb[i*3+2];
    }
    __syncthreads();

    const int q = blockIdx.x * 256 + threadIdx.x;
    const float* up = unknown + ((size_t)b * NPT + q) * 3;
    const float ux = up[0], uy = up[1], uz = up[2];

    float d0 = 1e30f, d1 = 1e30f, d2 = 1e30f;
    int   i0 = 0,     i1 = 0,     i2 = 0;
    #pragma unroll 4
    for (int i = 0; i < MPT; i++) {
        float dx = kx[i]-ux, dy = ky[i]-uy, dz = kz[i]-uz;
        float d = dx*dx + dy*dy + dz*dz;
        if (d < d2) {
            if (d < d1) {
                if (d < d0) { d2=d1; i2=i1; d1=d0; i1=i0; d0=d; i0=i; }
                else        { d2=d1; i2=i1; d1=d;  i1=i; }
            } else          { d2=d;  i2=i; }
        }
    }
    const float r0 = 1.f/(d0+1e-8f), r1 = 1.f/(d1+1e-8f), r2 = 1.f/(d2+1e-8f);
    const float s = 1.f/(r0+r1+r2);
    const int gi = b * NPT + q;
    g_idx[gi*3+0] = i0; g_idx[gi*3+1] = i1; g_idx[gi*3+2] = i2;
    g_w[gi*3+0] = r0*s; g_w[gi*3+1] = r1*s; g_w[gi*3+2] = r2*s;
}

// ---------------- transpose known_feats -> g_kft [b][m][c] ----------------
__global__ __launch_bounds__(256)
void tr_kf(const float* __restrict__ kf)
{
    __shared__ float t[32][33];
    const int b = blockIdx.z, m0 = blockIdx.x*32, c0 = blockIdx.y*32;
    const int x = threadIdx.x & 31, y0 = threadIdx.x >> 5;
    #pragma unroll
    for (int yy = 0; yy < 32; yy += 8)
        t[y0+yy][x] = kf[((size_t)b*C_ + c0+y0+yy)*MPT + m0 + x];
    __syncthreads();
    #pragma unroll
    for (int yy = 0; yy < 32; yy += 8)
        g_kft[((size_t)b*MPT + m0 + y0+yy)*C_ + c0 + x] = t[x][y0+yy];
}

// ---------------- transpose unknow_feats -> X[p][256+c] (tf32) ----------------
__global__ __launch_bounds__(256)
void tr_uf(const float* __restrict__ uf)
{
    __shared__ float t[32][33];
    const int b = blockIdx.z, j0 = blockIdx.x*32, c0 = blockIdx.y*32;
    const int x = threadIdx.x & 31, y0 = threadIdx.x >> 5;
    #pragma unroll
    for (int yy = 0; yy < 32; yy += 8)
        t[y0+yy][x] = uf[((size_t)b*C_ + c0+y0+yy)*NPT + j0 + x];
    __syncthreads();
    #pragma unroll
    for (int yy = 0; yy < 32; yy += 8)
        g_X[((size_t)b*NPT + j0 + y0+yy)*H_ + C_ + c0 + x] = tf32r(t[x][y0+yy]);
}

// ---------------- interpolate -> X[p][0..255] (tf32); warp per point ----------------
__global__ __launch_bounds__(256)
void interp_kernel()
{
    const int p = blockIdx.x * 8 + (threadIdx.x >> 5);
    const int lane = threadIdx.x & 31;
    const int b = p >> 13;

    const int   i0 = g_idx[p*3+0], i1 = g_idx[p*3+1], i2 = g_idx[p*3+2];
    const float w0 = g_w[p*3+0],   w1 = g_w[p*3+1],   w2 = g_w[p*3+2];

    const float* r0 = g_kft + ((size_t)b*MPT + i0)*C_ + lane*8;
    const float* r1 = g_kft + ((size_t)b*MPT + i1)*C_ + lane*8;
    const float* r2 = g_kft + ((size_t)b*MPT + i2)*C_ + lane*8;

    float4 a0 = *(const float4*)r0, a1 = *(const float4*)(r0+4);
    float4 c0 = *(const float4*)r1, c1 = *(const float4*)(r1+4);
    float4 e0 = *(const float4*)r2, e1 = *(const float4*)(r2+4);

    float4 o0, o1;
    o0.x = tf32r(w0*a0.x + w1*c0.x + w2*e0.x);
    o0.y = tf32r(w0*a0.y + w1*c0.y + w2*e0.y);
    o0.z = tf32r(w0*a0.z + w1*c0.z + w2*e0.z);
    o0.w = tf32r(w0*a0.w + w1*c0.w + w2*e0.w);
    o1.x = tf32r(w0*a1.x + w1*c1.x + w2*e1.x);
    o1.y = tf32r(w0*a1.y + w1*c1.y + w2*e1.y);
    o1.z = tf32r(w0*a1.z + w1*c1.z + w2*e1.z);
    o1.w = tf32r(w0*a1.w + w1*c1.w + w2*e1.w);

    float* xp = g_X + (size_t)p*H_ + lane*8;
    *(float4*)xp = o0;
    *(float4*)(xp+4) = o1;
}

// ---------------- tf32 mma.sync GEMM ----------------
// Out[o][p] = relu(BN(sum_k W[o][k] * Xn[p][k]))
// A = W row-major [m][k]; B = Xn [n][k] -> mma row.col directly.
// BM=128, BN=128, BK=32, 256 threads, 8 warps (2m x 4n), warp tile 64x32.
#define BK      32
#define LDT     36                         // row stride (floats), pad 4
#define TILE_F  (128*LDT)                  // floats per operand tile
#define STAGE_F (2*TILE_F)                 // A + B
#define NSTAGE  3
#define SMEMF   (NSTAGE*STAGE_F)           // 33,177.6.. = 3*9216 = 27648 floats (110592 B)

__device__ __forceinline__ void mma_tf32(float* c, const uint32_t* a, const uint32_t* b)
{
    asm volatile(
        "mma.sync.aligned.m16n8k8.row.col.f32.tf32.tf32.f32 "
        "{%0,%1,%2,%3}, {%4,%5,%6,%7}, {%8,%9}, {%0,%1,%2,%3};"
        : "+f"(c[0]), "+f"(c[1]), "+f"(c[2]), "+f"(c[3])
        : "r"(a[0]), "r"(a[1]), "r"(a[2]), "r"(a[3]), "r"(b[0]), "r"(b[1]));
}

__device__ __forceinline__ void load_stage(const float* __restrict__ A, const float* __restrict__ Xn,
                                           int m0, int n0, int kt, float* sA, float* sB, int tid)
{
    const int k0 = kt * BK;
    #pragma unroll
    for (int i = 0; i < 4; i++) {
        int idx = tid + i*256;             // 0..1023
        int row = idx >> 3;                // 0..127
        int c   = idx & 7;                 // 16B chunk
        cp16(sA + row*LDT + c*4, A  + (size_t)(m0 + row)*H_ + k0 + c*4);
    }
    #pragma unroll
    for (int i = 0; i < 4; i++) {
        int idx = tid + i*256;
        int row = idx >> 3;
        int c   = idx & 7;
        cp16(sB + row*LDT + c*4, Xn + (size_t)(n0 + row)*H_ + k0 + c*4);
    }
    asm volatile("cp.async.commit_group;\n");
}

__global__ __launch_bounds__(256, 1)
void gemm_tc(const float* __restrict__ A, const float* __restrict__ Xn, float* __restrict__ Out,
             const float* __restrict__ G, const float* __restrict__ Bb,
             const float* __restrict__ Mu, const float* __restrict__ Va, int mode)
{
    extern __shared__ float sm[];
    const int tid  = threadIdx.x;
    const int wid  = tid >> 5;
    const int lane = tid & 31;
    const int g    = lane >> 2;            // 0..7
    const int ctib = lane & 3;             // 0..3
    const int wm0  = (wid >> 2) * 64;      // warp m offset in tile
    const int wn0  = (wid & 3)  * 32;      // warp n offset in tile
    const int n0   = blockIdx.x * 128;
    const int m0   = blockIdx.y * 128;

    float acc[4][4][4];                    // [mt][nt][4]
    #pragma unroll
    for (int mt = 0; mt < 4; mt++)
        #pragma unroll
        for (int nt = 0; nt < 4; nt++)
            #pragma unroll
            for (int q = 0; q < 4; q++) acc[mt][nt][q] = 0.0f;

    load_stage(A, Xn, m0, n0, 0, sm, sm + TILE_F, tid);
    load_stage(A, Xn, m0, n0, 1, sm + STAGE_F, sm + STAGE_F + TILE_F, tid);
    load_stage(A, Xn, m0, n0, 2, sm + 2*STAGE_F, sm + 2*STAGE_F + TILE_F, tid);

    for (int kt = 0; kt < 16; kt++) {
        if (kt <= 13)      asm volatile("cp.async.wait_group 2;\n");
        else if (kt == 14) asm volatile("cp.async.wait_group 1;\n");
        else               asm volatile("cp.async.wait_group 0;\n");
        __syncthreads();

        const float* sA = sm + (kt % NSTAGE) * STAGE_F;
        const float* sB = sA + TILE_F;

        #pragma unroll
        for (int kk = 0; kk < 4; kk++) {
            const int kb = kk * 8;
            uint32_t af[4][4], bf[4][2];
            #pragma unroll
            for (int mt = 0; mt < 4; mt++) {
                const float* p0 = sA + (wm0 + mt*16 + g)*LDT + kb + ctib;
                af[mt][0] = __float_as_uint(p0[0]);
                af[mt][1] = __float_as_uint(p0[8*LDT]);
                af[mt][2] = __float_as_uint(p0[4]);
                af[mt][3] = __float_as_uint(p0[8*LDT + 4]);
            }
            #pragma unroll
            for (int nt = 0; nt < 4; nt++) {
                const float* p0 = sB + (wn0 + nt*8 + g)*LDT + kb + ctib;
                bf[nt][0] = __float_as_uint(p0[0]);
                bf[nt][1] = __float_as_uint(p0[4]);
            }
            #pragma unroll
            for (int mt = 0; mt < 4; mt++)
                #pragma unroll
                for (int nt = 0; nt < 4; nt++)
                    mma_tf32(acc[mt][nt], af[mt], bf[nt]);
        }
        __syncthreads();
        if (kt + 3 < 16)
            load_stage(A, Xn, m0, n0, kt + 3,
                       sm + (kt % NSTAGE) * STAGE_F,
                       sm + (kt % NSTAGE) * STAGE_F + TILE_F, tid);
    }

    // -------- epilogue: BN + ReLU, stage through smem for coalesced writes --------
    __syncthreads();
    float* patch = sm + wid * 2304;        // 9216 B per warp

    if (mode == 0) {
        // patch layout [n][m], stride 68 (32 x 64)
        #pragma unroll
        for (int mt = 0; mt < 4; mt++) {
            const int o0 = m0 + wm0 + mt*16 + g;
            const float sc0 = G[o0]   * rsqrtf(Va[o0]   + 1e-5f);
            const float sh0 = Bb[o0]   - Mu[o0]  * sc0;
            const float sc1 = G[o0+8] * rsqrtf(Va[o0+8] + 1e-5f);
            const float sh1 = Bb[o0+8] - Mu[o0+8] * sc1;
            #pragma unroll
            for (int nt = 0; nt < 4; nt++) {
                const int nl = nt*8 + 2*ctib;
                const int ml = mt*16 + g;
                patch[ nl   *68 + ml  ] = tf32r(fmaxf(fmaf(acc[mt][nt][0], sc0, sh0), 0.f));
                patch[(nl+1)*68 + ml  ] = tf32r(fmaxf(fmaf(acc[mt][nt][1], sc0, sh0), 0.f));
                patch[ nl   *68 + ml+8] = tf32r(fmaxf(fmaf(acc[mt][nt][2], sc1, sh1), 0.f));
                patch[(nl+1)*68 + ml+8] = tf32r(fmaxf(fmaf(acc[mt][nt][3], sc1, sh1), 0.f));
            }
        }
        __syncwarp();
        float* yb = Out + (size_t)(n0 + wn0) * H_ + m0 + wm0;
        #pragma unroll
        for (int r = 0; r < 32; r++)
            *(float2*)(yb + (size_t)r * H_ + lane*2) = *(float2*)(patch + r*68 + lane*2);
    } else {
        // patch layout [m][n], stride 36 (64 x 32)
        #pragma unroll
        for (int mt = 0; mt < 4; mt++) {
            const int o0 = m0 + wm0 + mt*16 + g;
            const float sc0 = G[o0]   * rsqrtf(Va[o0]   + 1e-5f);
            const float sh0 = Bb[o0]   - Mu[o0]  * sc0;
            const float sc1 = G[o0+8] * rsqrtf(Va[o0+8] + 1e-5f);
            const float sh1 = Bb[o0+8] - Mu[o0+8] * sc1;
            #pragma unroll
            for (int nt = 0; nt < 4; nt++) {
                const int nl = nt*8 + 2*ctib;
                const int ml = mt*16 + g;
                patch[ ml   *36 + nl  ] = fmaxf(fmaf(acc[mt][nt][0], sc0, sh0), 0.f);
                patch[ ml   *36 + nl+1] = fmaxf(fmaf(acc[mt][nt][1], sc0, sh0), 0.f);
                patch[(ml+8)*36 + nl  ] = fmaxf(fmaf(acc[mt][nt][2], sc1, sh1), 0.f);
                patch[(ml+8)*36 + nl+1] = fmaxf(fmaf(acc[mt][nt][3], sc1, sh1), 0.f);
            }
        }
        __syncwarp();
        const int b  = n0 >> 13;
        const int j0 = (n0 & (NPT-1)) + wn0;
        float* ob = Out + ((size_t)b * H_ + m0 + wm0) * NPT + j0;
        #pragma unroll
        for (int r = 0; r < 64; r++)
            ob[(size_t)r * NPT + lane] = patch[r*36 + lane];
    }
}

// ---------------- launch ----------------
extern "C" void kernel_launch(void* const* d_in, const int* in_sizes, int n_in,
                              void* d_out, int out_size)
{
    const float* unknown      = (const float*)d_in[0];
    const float* known        = (const float*)d_in[1];
    const float* unknow_feats = (const float*)d_in[2];
    const float* known_feats  = (const float*)d_in[3];
    const float* W1 = (const float*)d_in[4];
    const float* g1 = (const float*)d_in[5];
    const float* b1 = (const float*)d_in[6];
    const float* m1 = (const float*)d_in[7];
    const float* v1 = (const float*)d_in[8];
    const float* W2 = (const float*)d_in[9];
    const float* g2 = (const float*)d_in[10];
    const float* b2 = (const float*)d_in[11];
    const float* m2 = (const float*)d_in[12];
    const float* v2 = (const float*)d_in[13];
    float* out = (float*)d_out;

    float* X;  cudaGetSymbolAddress((void**)&X,  g_X);
    float* Y;  cudaGetSymbolAddress((void**)&Y,  g_Y);
    float* Wa; cudaGetSymbolAddress((void**)&Wa, g_W1r);
    float* Wb; cudaGetSymbolAddress((void**)&Wb, g_W2r);

    const int smem_bytes = SMEMF * 4;      // 110592
    cudaFuncSetAttribute(gemm_tc, cudaFuncAttributeMaxDynamicSharedMemorySize, smem_bytes);

    round_w<<<1024, 256>>>(W1, W2);
    knn_kernel<<<dim3(NPT/256, B_), 256>>>(unknown, known);
    tr_kf<<<dim3(MPT/32, C_/32, B_), 256>>>(known_feats);
    tr_uf<<<dim3(NPT/32, C_/32, B_), 256>>>(unknow_feats);
    interp_kernel<<<NTOT/8, 256>>>();

    gemm_tc<<<dim3(NTOT/128, 4), 256, smem_bytes>>>(Wa, X, Y,   g1, b1, m1, v1, 0);
    gemm_tc<<<dim3(NTOT/128, 4), 256, smem_bytes>>>(Wb, Y, out, g2, b2, m2, v2, 1);

    (void)in_sizes; (void)n_in; (void)out_size;
}

// round 4
// speedup vs baseline: 3.0183x; 1.1666x over previous
#include <cuda_runtime.h>
#include <cstdint>
#include <math.h>

#define B_    8
#define NPT   8192
#define MPT   2048
#define C_    256
#define H_    512
#define NTOT  (B_*NPT)

// ---------------- scratch ----------------
__device__ float g_X[(size_t)NTOT * H_];          // [p][perm(k)] layer-1 input (tf32)
__device__ float g_Y[(size_t)NTOT * H_];          // [p][perm(o)] layer-1 output (tf32)
__device__ float g_kft[(size_t)B_ * MPT * C_];    // known_feats transposed [b][m][c]
__device__ float g_W1r[H_ * H_];                  // tf32, k-permuted cols
__device__ float g_W2r[H_ * H_];                  // tf32, k-permuted cols
__device__ int   g_idx[NTOT * 3];
__device__ float g_w[NTOT * 3];

__device__ __forceinline__ float tf32r(float x) {
    asm("cvt.rna.tf32.f32 %0, %1;" : "=f"(x) : "f"(x));
    return x;
}
// k-permutation within each 8-group: [k0,k4,k1,k5,k2,k6,k3,k7]
__device__ __forceinline__ int perm8(int k) {
    return (k & ~7) | ((k & 3) << 1) | ((k >> 2) & 1);
}
__device__ __forceinline__ void cp16(void* s, const void* g) {
    uint32_t a;
    asm("{ .reg .u64 t; cvta.to.shared.u64 t, %1; cvt.u32.u64 %0, t; }" : "=r"(a) : "l"(s));
    asm volatile("cp.async.cg.shared.global [%0], [%1], 16;\n" :: "r"(a), "l"(g));
}

// ---------------- round weights to tf32, permute k columns ----------------
__global__ __launch_bounds__(256)
void round_w(const float* __restrict__ W1, const float* __restrict__ W2)
{
    int i = blockIdx.x * 256 + threadIdx.x;
    int o = i >> 9, k = i & 511;
    g_W1r[o * H_ + perm8(k)] = tf32r(W1[i]);
    g_W2r[o * H_ + perm8(k)] = tf32r(W2[i]);
}

// ---------------- 3-NN + weights ----------------
__global__ __launch_bounds__(256)
void knn_kernel(const float* __restrict__ unknown, const float* __restrict__ known)
{
    __shared__ float kx[MPT], ky[MPT], kz[MPT];
    const int b = blockIdx.y;
    const float* kb = known + (size_t)b * MPT * 3;
    for (int i = threadIdx.x; i < MPT; i += 256) {
        kx[i] = kb[i*3+0]; ky[i] = kb[i*3+1]; kz[i] = kb[i*3+2];
    }
    __syncthreads();

    const int q = blockIdx.x * 256 + threadIdx.x;
    const float* up = unknown + ((size_t)b * NPT + q) * 3;
    const float ux = up[0], uy = up[1], uz = up[2];

    float d0 = 1e30f, d1 = 1e30f, d2 = 1e30f;
    int   i0 = 0,     i1 = 0,     i2 = 0;
    #pragma unroll 4
    for (int i = 0; i < MPT; i++) {
        float dx = kx[i]-ux, dy = ky[i]-uy, dz = kz[i]-uz;
        float d = dx*dx + dy*dy + dz*dz;
        if (d < d2) {
            if (d < d1) {
                if (d < d0) { d2=d1; i2=i1; d1=d0; i1=i0; d0=d; i0=i; }
                else        { d2=d1; i2=i1; d1=d;  i1=i; }
            } else          { d2=d;  i2=i; }
        }
    }
    const float r0 = 1.f/(d0+1e-8f), r1 = 1.f/(d1+1e-8f), r2 = 1.f/(d2+1e-8f);
    const float s = 1.f/(r0+r1+r2);
    const int gi = b * NPT + q;
    g_idx[gi*3+0] = i0; g_idx[gi*3+1] = i1; g_idx[gi*3+2] = i2;
    g_w[gi*3+0] = r0*s; g_w[gi*3+1] = r1*s; g_w[gi*3+2] = r2*s;
}

// ---------------- transpose known_feats -> g_kft [b][m][c] ----------------
__global__ __launch_bounds__(256)
void tr_kf(const float* __restrict__ kf)
{
    __shared__ float t[32][33];
    const int b = blockIdx.z, m0 = blockIdx.x*32, c0 = blockIdx.y*32;
    const int x = threadIdx.x & 31, y0 = threadIdx.x >> 5;
    #pragma unroll
    for (int yy = 0; yy < 32; yy += 8)
        t[y0+yy][x] = kf[((size_t)b*C_ + c0+y0+yy)*MPT + m0 + x];
    __syncthreads();
    #pragma unroll
    for (int yy = 0; yy < 32; yy += 8)
        g_kft[((size_t)b*MPT + m0 + y0+yy)*C_ + c0 + x] = t[x][y0+yy];
}

// ---------------- transpose unknow_feats -> X[p][perm(256+c)] (tf32) ----------------
__global__ __launch_bounds__(256)
void tr_uf(const float* __restrict__ uf)
{
    __shared__ float t[32][33];
    const int b = blockIdx.z, j0 = blockIdx.x*32, c0 = blockIdx.y*32;
    const int x = threadIdx.x & 31, y0 = threadIdx.x >> 5;
    #pragma unroll
    for (int yy = 0; yy < 32; yy += 8)
        t[y0+yy][x] = uf[((size_t)b*C_ + c0+y0+yy)*NPT + j0 + x];
    __syncthreads();
    #pragma unroll
    for (int yy = 0; yy < 32; yy += 8)
        g_X[((size_t)b*NPT + j0 + y0+yy)*H_ + C_ + perm8(c0 + x)] = tf32r(t[x][y0+yy]);
}

// ---------------- interpolate -> X[p][perm(0..255)] (tf32); warp per point ----------------
__global__ __launch_bounds__(256)
void interp_kernel()
{
    const int p = blockIdx.x * 8 + (threadIdx.x >> 5);
    const int lane = threadIdx.x & 31;
    const int b = p >> 13;

    const int   i0 = g_idx[p*3+0], i1 = g_idx[p*3+1], i2 = g_idx[p*3+2];
    const float w0 = g_w[p*3+0],   w1 = g_w[p*3+1],   w2 = g_w[p*3+2];

    const float* r0 = g_kft + ((size_t)b*MPT + i0)*C_ + lane*8;
    const float* r1 = g_kft + ((size_t)b*MPT + i1)*C_ + lane*8;
    const float* r2 = g_kft + ((size_t)b*MPT + i2)*C_ + lane*8;

    float4 a0 = *(const float4*)r0, a1 = *(const float4*)(r0+4);
    float4 c0 = *(const float4*)r1, c1 = *(const float4*)(r1+4);
    float4 e0 = *(const float4*)r2, e1 = *(const float4*)(r2+4);

    float lo[4], hi[4];
    lo[0] = tf32r(w0*a0.x + w1*c0.x + w2*e0.x);
    lo[1] = tf32r(w0*a0.y + w1*c0.y + w2*e0.y);
    lo[2] = tf32r(w0*a0.z + w1*c0.z + w2*e0.z);
    lo[3] = tf32r(w0*a0.w + w1*c0.w + w2*e0.w);
    hi[0] = tf32r(w0*a1.x + w1*c1.x + w2*e1.x);
    hi[1] = tf32r(w0*a1.y + w1*c1.y + w2*e1.y);
    hi[2] = tf32r(w0*a1.z + w1*c1.z + w2*e1.z);
    hi[3] = tf32r(w0*a1.w + w1*c1.w + w2*e1.w);

    // permuted within the 8-group: cols [k0,k4,k1,k5 | k2,k6,k3,k7]
    float4 o0 = make_float4(lo[0], hi[0], lo[1], hi[1]);
    float4 o1 = make_float4(lo[2], hi[2], lo[3], hi[3]);
    float* xp = g_X + (size_t)p*H_ + lane*8;
    *(float4*)xp = o0;
    *(float4*)(xp+4) = o1;
}

// ---------------- tf32 mma.sync GEMM: BM=128, BN=256, BK=32, warp 64x64 ----------------
#define LDT     40                         // row stride floats (pad 8) - conflict-free LDS.64
#define A_F     (128*LDT)                  // 5120 floats
#define B_F     (256*LDT)                  // 10240 floats
#define STAGE_F (A_F + B_F)                // 15360 floats (61440 B)
#define NSTAGE  3
#define SMEMB   (NSTAGE*STAGE_F*4)         // 184320 B

__device__ __forceinline__ void mma_tf32(float* c, const uint32_t* a, const uint32_t* b)
{
    asm volatile(
        "mma.sync.aligned.m16n8k8.row.col.f32.tf32.tf32.f32 "
        "{%0,%1,%2,%3}, {%4,%5,%6,%7}, {%8,%9}, {%0,%1,%2,%3};"
        : "+f"(c[0]), "+f"(c[1]), "+f"(c[2]), "+f"(c[3])
        : "r"(a[0]), "r"(a[1]), "r"(a[2]), "r"(a[3]), "r"(b[0]), "r"(b[1]));
}

__device__ __forceinline__ void load_stage(const float* __restrict__ A, const float* __restrict__ Xn,
                                           int m0, int n0, int kt, float* st, int tid)
{
    const int k0 = kt * 32;
    float* sA = st;
    float* sB = st + A_F;
    #pragma unroll
    for (int i = 0; i < 4; i++) {
        int idx = tid + i*256;             // 0..1023
        int row = idx >> 3;                // 0..127
        int c   = idx & 7;
        cp16(sA + row*LDT + c*4, A + (size_t)(m0 + row)*H_ + k0 + c*4);
    }
    #pragma unroll
    for (int i = 0; i < 8; i++) {
        int idx = tid + i*256;             // 0..2047
        int row = idx >> 3;                // 0..255
        int c   = idx & 7;
        cp16(sB + row*LDT + c*4, Xn + (size_t)(n0 + row)*H_ + k0 + c*4);
    }
    asm volatile("cp.async.commit_group;\n");
}

__global__ __launch_bounds__(256, 1)
void gemm_tc(const float* __restrict__ A, const float* __restrict__ Xn, float* __restrict__ Out,
             const float* __restrict__ G, const float* __restrict__ Bb,
             const float* __restrict__ Mu, const float* __restrict__ Va, int mode)
{
    extern __shared__ float sm[];
    const int tid  = threadIdx.x;
    const int wid  = tid >> 5;
    const int lane = tid & 31;
    const int g    = lane >> 2;
    const int ctib = lane & 3;
    const int wm0  = (wid >> 2) * 64;      // 0 or 64
    const int wn0  = (wid & 3)  * 64;      // 0..192
    const int n0   = blockIdx.x * 256;
    const int m0   = blockIdx.y * 128;

    float acc[4][8][4];
    #pragma unroll
    for (int mt = 0; mt < 4; mt++)
        #pragma unroll
        for (int nt = 0; nt < 8; nt++)
            #pragma unroll
            for (int q = 0; q < 4; q++) acc[mt][nt][q] = 0.0f;

    load_stage(A, Xn, m0, n0, 0, sm, tid);
    load_stage(A, Xn, m0, n0, 1, sm + STAGE_F, tid);
    load_stage(A, Xn, m0, n0, 2, sm + 2*STAGE_F, tid);

    for (int kt = 0; kt < 16; kt++) {
        if (kt <= 13)      asm volatile("cp.async.wait_group 2;\n");
        else if (kt == 14) asm volatile("cp.async.wait_group 1;\n");
        else               asm volatile("cp.async.wait_group 0;\n");
        __syncthreads();

        const float* sA = sm + (kt % NSTAGE) * STAGE_F;
        const float* sB = sA + A_F;

        #pragma unroll
        for (int kk = 0; kk < 4; kk++) {
            const int kb = kk * 8;
            uint32_t af[4][4], bf[8][2];
            #pragma unroll
            for (int mt = 0; mt < 4; mt++) {
                const float* pa = sA + (wm0 + mt*16 + g)*LDT + kb + 2*ctib;
                float2 lo = *(const float2*)pa;            // a0 (k=ctib), a2 (k=ctib+4)
                float2 hi = *(const float2*)(pa + 8*LDT);  // a1, a3
                af[mt][0] = __float_as_uint(lo.x);
                af[mt][1] = __float_as_uint(hi.x);
                af[mt][2] = __float_as_uint(lo.y);
                af[mt][3] = __float_as_uint(hi.y);
            }
            #pragma unroll
            for (int nt = 0; nt < 8; nt++) {
                float2 bb = *(const float2*)(sB + (wn0 + nt*8 + g)*LDT + kb + 2*ctib);
                bf[nt][0] = __float_as_uint(bb.x);
                bf[nt][1] = __float_as_uint(bb.y);
            }
            #pragma unroll
            for (int mt = 0; mt < 4; mt++)
                #pragma unroll
                for (int nt = 0; nt < 8; nt++)
                    mma_tf32(acc[mt][nt], af[mt], bf[nt]);
        }
        __syncthreads();
        if (kt + 3 < 16)
            load_stage(A, Xn, m0, n0, kt + 3, sm + (kt % NSTAGE) * STAGE_F, tid);
    }

    // -------- epilogue: BN + ReLU, staged through smem --------
    __syncthreads();
    float* patch = sm + wid * 4224;        // 64*66 floats per warp

    if (mode == 0) {
        // patch [n][m] 64x64, m positions k-permuted (Y feeds layer-2 as k)
        #pragma unroll
        for (int mt = 0; mt < 4; mt++) {
            const int o0 = m0 + wm0 + mt*16 + g;
            const float sc0 = G[o0]   * rsqrtf(Va[o0]   + 1e-5f);
            const float sh0 = Bb[o0]   - Mu[o0]  * sc0;
            const float sc1 = G[o0+8] * rsqrtf(Va[o0+8] + 1e-5f);
            const float sh1 = Bb[o0+8] - Mu[o0+8] * sc1;
            const int ml  = perm8(mt*16 + g);
            const int mlh = perm8(mt*16 + g + 8);
            #pragma unroll
            for (int nt = 0; nt < 8; nt++) {
                const int nl = nt*8 + 2*ctib;
                patch[ nl   *66 + ml ] = tf32r(fmaxf(fmaf(acc[mt][nt][0], sc0, sh0), 0.f));
                patch[(nl+1)*66 + ml ] = tf32r(fmaxf(fmaf(acc[mt][nt][1], sc0, sh0), 0.f));
                patch[ nl   *66 + mlh] = tf32r(fmaxf(fmaf(acc[mt][nt][2], sc1, sh1), 0.f));
                patch[(nl+1)*66 + mlh] = tf32r(fmaxf(fmaf(acc[mt][nt][3], sc1, sh1), 0.f));
            }
        }
        __syncwarp();
        float* yb = Out + (size_t)(n0 + wn0) * H_ + m0 + wm0;
        #pragma unroll
        for (int r = 0; r < 64; r++)
            *(float2*)(yb + (size_t)r * H_ + lane*2) = *(float2*)(patch + r*66 + lane*2);
    } else {
        // patch [m][n] 64x64, physical layout
        #pragma unroll
        for (int mt = 0; mt < 4; mt++) {
            const int o0 = m0 + wm0 + mt*16 + g;
            const float sc0 = G[o0]   * rsqrtf(Va[o0]   + 1e-5f);
            const float sh0 = Bb[o0]   - Mu[o0]  * sc0;
            const float sc1 = G[o0+8] * rsqrtf(Va[o0+8] + 1e-5f);
            const float sh1 = Bb[o0+8] - Mu[o0+8] * sc1;
            const int ml = mt*16 + g;
            #pragma unroll
            for (int nt = 0; nt < 8; nt++) {
                const int nl = nt*8 + 2*ctib;
                patch[ ml   *66 + nl  ] = fmaxf(fmaf(acc[mt][nt][0], sc0, sh0), 0.f);
                patch[ ml   *66 + nl+1] = fmaxf(fmaf(acc[mt][nt][1], sc0, sh0), 0.f);
                patch[(ml+8)*66 + nl  ] = fmaxf(fmaf(acc[mt][nt][2], sc1, sh1), 0.f);
                patch[(ml+8)*66 + nl+1] = fmaxf(fmaf(acc[mt][nt][3], sc1, sh1), 0.f);
            }
        }
        __syncwarp();
        const int b  = n0 >> 13;
        const int j0 = (n0 & (NPT-1)) + wn0;
        float* ob = Out + ((size_t)b * H_ + m0 + wm0) * NPT + j0;
        #pragma unroll
        for (int r = 0; r < 64; r++)
            *(float2*)(ob + (size_t)r * NPT + lane*2) = *(float2*)(patch + r*66 + lane*2);
    }
}

// ---------------- launch ----------------
extern "C" void kernel_launch(void* const* d_in, const int* in_sizes, int n_in,
                              void* d_out, int out_size)
{
    const float* unknown      = (const float*)d_in[0];
    const float* known        = (const float*)d_in[1];
    const float* unknow_feats = (const float*)d_in[2];
    const float* known_feats  = (const float*)d_in[3];
    const float* W1 = (const float*)d_in[4];
    const float* g1 = (const float*)d_in[5];
    const float* b1 = (const float*)d_in[6];
    const float* m1 = (const float*)d_in[7];
    const float* v1 = (const float*)d_in[8];
    const float* W2 = (const float*)d_in[9];
    const float* g2 = (const float*)d_in[10];
    const float* b2 = (const float*)d_in[11];
    const float* m2 = (const float*)d_in[12];
    const float* v2 = (const float*)d_in[13];
    float* out = (float*)d_out;

    float* X;  cudaGetSymbolAddress((void**)&X,  g_X);
    float* Y;  cudaGetSymbolAddress((void**)&Y,  g_Y);
    float* Wa; cudaGetSymbolAddress((void**)&Wa, g_W1r);
    float* Wb; cudaGetSymbolAddress((void**)&Wb, g_W2r);

    cudaFuncSetAttribute(gemm_tc, cudaFuncAttributeMaxDynamicSharedMemorySize, SMEMB);

    round_w<<<1024, 256>>>(W1, W2);
    knn_kernel<<<dim3(NPT/256, B_), 256>>>(unknown, known);
    tr_kf<<<dim3(MPT/32, C_/32, B_), 256>>>(known_feats);
    tr_uf<<<dim3(NPT/32, C_/32, B_), 256>>>(unknow_feats);
    interp_kernel<<<NTOT/8, 256>>>();

    gemm_tc<<<dim3(NTOT/256, 4), 256, SMEMB>>>(Wa, X, Y,   g1, b1, m1, v1, 0);
    gemm_tc<<<dim3(NTOT/256, 4), 256, SMEMB>>>(Wb, Y, out, g2, b2, m2, v2, 1);

    (void)in_sizes; (void)n_in; (void)out_size;
}